// round 9
// baseline (speedup 1.0000x reference)
#include <cuda_runtime.h>
#include <cuda_fp16.h>
#include <cuda.h>
#include <cstdint>

#define N_DIM   11008
#define K_DIM   4096
#define KW      2048      // int32 words per weight row
#define M_DIM   32
#define NT      86        // n-tiles
#define NKU     8         // k-eighths
#define UNITS   (NT * NKU)   // 688
#define GRID    148
#define NSTAGE  4
// stage layout: A_lo 16K | A_hi 16K | x_lo 4K | x_hi 4K  = 40960 B
#define STAGEB  40960
#define A_HI    16384
#define X_LO    32768
#define X_HI    36864
#define MBAR_OFF (NSTAGE * STAGEB)       // 163840
#define SMEM_TOTAL (MBAR_OFF + 64)
#define NCONS   128                      // consumer threads (warps 0-3)

__device__ __half g_x16[M_DIM * K_DIM];            // fp16 copy of x
__device__ float  g_part[NKU][M_DIM * N_DIM];      // k-split partials (fp32)

__device__ __forceinline__ uint32_t lds32(uint32_t a) {
    uint32_t v; asm volatile("ld.shared.b32 %0, [%1];" : "=r"(v) : "r"(a)); return v;
}
__device__ __forceinline__ uint32_t cvt_pair(uint32_t w) {
    uint32_t p = ((w | (w << 12)) & 0x000F000Fu) | 0x64006400u;
    uint32_t r;
    asm("sub.f16x2 %0, %1, %2;" : "=r"(r) : "r"(p), "r"(0x64086408u));
    return r;
}
__device__ __forceinline__ void mma16816(float* d,
    uint32_t a0, uint32_t a1, uint32_t a2, uint32_t a3,
    uint32_t b0, uint32_t b1) {
    asm volatile(
        "mma.sync.aligned.m16n8k16.row.col.f32.f16.f16.f32 "
        "{%0,%1,%2,%3}, {%4,%5,%6,%7}, {%8,%9}, {%0,%1,%2,%3};"
        : "+f"(d[0]), "+f"(d[1]), "+f"(d[2]), "+f"(d[3])
        : "r"(a0), "r"(a1), "r"(a2), "r"(a3), "r"(b0), "r"(b1));
}
__device__ __forceinline__ void mbar_init(uint32_t a, uint32_t cnt) {
    asm volatile("mbarrier.init.shared.b64 [%0], %1;" :: "r"(a), "r"(cnt) : "memory");
}
__device__ __forceinline__ void mbar_arrive(uint32_t a) {
    asm volatile("mbarrier.arrive.shared.b64 _, [%0];" :: "r"(a) : "memory");
}
__device__ __forceinline__ void mbar_expect_tx(uint32_t a, uint32_t bytes) {
    asm volatile("mbarrier.arrive.expect_tx.shared.b64 _, [%0], %1;"
                 :: "r"(a), "r"(bytes) : "memory");
}
__device__ __forceinline__ void mbar_wait(uint32_t a, uint32_t parity) {
    asm volatile(
        "{\n\t.reg .pred P;\n\t"
        "LAB_%=:\n\t"
        "mbarrier.try_wait.parity.acquire.cta.shared::cta.b64 P, [%0], %1, 0x989680;\n\t"
        "@!P bra LAB_%=;\n\t}"
        :: "r"(a), "r"(parity) : "memory");
}
__device__ __forceinline__ void tma2d(uint32_t dst, const CUtensorMap* tm,
                                      int cx, int cy, uint32_t mbar) {
    asm volatile(
        "cp.async.bulk.tensor.2d.shared::cta.global.tile.mbarrier::complete_tx::bytes "
        "[%0], [%1, {%2, %3}], [%4];"
        :: "r"(dst), "l"(tm), "r"(cx), "r"(cy), "r"(mbar) : "memory");
}

extern __shared__ char smem_raw[];

__global__ void cvt_x_kernel(const float* __restrict__ x) {
    int i = (blockIdx.x * blockDim.x + threadIdx.x) * 4;   // 128x256x4 = 131072
    float4 v = *reinterpret_cast<const float4*>(x + i);
    __half2 h0 = __floats2half2_rn(v.x, v.y);
    __half2 h1 = __floats2half2_rn(v.z, v.w);
    *reinterpret_cast<uint2*>(g_x16 + i) =
        make_uint2(*(uint32_t*)&h0, *(uint32_t*)&h1);
}

__global__ void finalize_kernel(float* __restrict__ out) {
    int i = (blockIdx.x * blockDim.x + threadIdx.x) * 4;
    if (i < M_DIM * N_DIM) {
        float4 v = *reinterpret_cast<const float4*>(&g_part[0][i]);
        #pragma unroll
        for (int k = 1; k < NKU; k++) {
            float4 p = *reinterpret_cast<const float4*>(&g_part[k][i]);
            v.x += p.x; v.y += p.y; v.z += p.z; v.w += p.w;
        }
        v.x = __half2float(__float2half(v.x));
        v.y = __half2float(__float2half(v.y));
        v.z = __half2float(__float2half(v.z));
        v.w = __half2float(__float2half(v.w));
        *reinterpret_cast<float4*>(out + i) = v;
    }
}

__global__ void __launch_bounds__(160, 1)
w4a16_mma_kernel(const __grid_constant__ CUtensorMap tmA,
                 const __grid_constant__ CUtensorMap tmX,
                 const float* __restrict__ sc) {
    const int tid = threadIdx.x;
    const int cta = blockIdx.x;
    const uint32_t sb = (uint32_t)__cvta_generic_to_shared(smem_raw);
    const uint32_t mb = sb + MBAR_OFF;   // full[0..3] at +0..+24, empty[0..3] at +32..+56

    if (tid == 0) {
        #pragma unroll
        for (int s = 0; s < NSTAGE; s++) {
            mbar_init(mb + s * 8, 1);               // full[s]
            mbar_init(mb + 32 + s * 8, NCONS);      // empty[s]
        }
    }
    __syncthreads();

    if (tid >= NCONS) {
        // ================== PRODUCER (one thread issues TMA) ==================
        if (tid == NCONS) {
            int lc = 0;
            #pragma unroll 1
            for (int gu = cta; gu < UNITS; gu += GRID) {
                const int nt = gu % NT;
                const int ku = gu / NT;
                const int nb = nt * 128;
                #pragma unroll 1
                for (int cp = 0; cp < 4; cp++, lc++) {
                    const int s = lc & (NSTAGE - 1);
                    mbar_wait(mb + 32 + s * 8, 1u ^ ((lc >> 2) & 1));
                    const uint32_t full = mb + s * 8;
                    const uint32_t st = sb + (uint32_t)s * STAGEB;
                    const int c = ku * 4 + cp;
                    mbar_expect_tx(full, STAGEB);
                    tma2d(st,        &tmA, c * 64,       nb, full);
                    tma2d(st + A_HI, &tmA, c * 64 + 32,  nb, full);
                    tma2d(st + X_LO, &tmX, c * 128,      0,  full);
                    tma2d(st + X_HI, &tmX, c * 128 + 64, 0,  full);
                }
            }
        }
        return;
    }

    // ================== CONSUMER (warps 0-3, 32 N-rows each) ==================
    const int warp = tid >> 5;
    const int lane = tid & 31;
    const int g = lane >> 2;
    const int t = lane & 3;

    // swizzle-folded per-thread base (rows r0+8j all have row&7 == g)
    const uint32_t thr = 4 * t + 16 * (g & 1) + 32 * (g >> 1);
    const int r0 = warp * 32 + g;

    int lc = 0;
    #pragma unroll 1
    for (int gu = cta; gu < UNITS; gu += GRID) {
        const int nt = gu % NT;
        const int ku = gu / NT;
        const int nb = nt * 128;

        float acc0[4][4], acc1[4][4];
        #pragma unroll
        for (int i = 0; i < 4; i++)
            #pragma unroll
            for (int j = 0; j < 4; j++) { acc0[i][j] = 0.0f; acc1[i][j] = 0.0f; }

        const size_t scR0 = (size_t)(nb + r0) * 32 + ku * 4;   // row r0
        const size_t scR1 = scR0 + 8 * 32;                     // row r0+8
        const size_t scR2 = scR0 + 16 * 32;                    // row r0+16
        const size_t scR3 = scR0 + 24 * 32;                    // row r0+24

        #pragma unroll 1
        for (int cp = 0; cp < 4; cp++, lc++) {
            const int s = lc & (NSTAGE - 1);
            mbar_wait(mb + s * 8, (lc >> 2) & 1);

            float s0 = sc[scR0 + cp];
            float s1 = sc[scR1 + cp];
            float s2 = sc[scR2 + cp];
            float s3 = sc[scR3 + cp];

            const uint32_t st = sb + (uint32_t)s * STAGEB;
            const uint32_t a0 = st + (uint32_t)r0 * 128 + thr;   // row r0
            const uint32_t a1 = a0 + 8 * 128;                    // r0+8
            const uint32_t a2 = a0 + 16 * 128;                   // r0+16
            const uint32_t a3 = a0 + 24 * 128;                   // r0+24
            const uint32_t xq0 = st + X_LO + (uint32_t)g * 128 + thr;

            float dd0[4][4], dd1[4][4];
            #pragma unroll
            for (int a = 0; a < 4; a++)
                #pragma unroll
                for (int b = 0; b < 4; b++) { dd0[a][b] = 0.0f; dd1[a][b] = 0.0f; }

            #pragma unroll
            for (int ss = 0; ss < 8; ss++) {
                const uint32_t Aoff = (ss >> 2) ? A_HI : 0;
                const uint32_t Xoff = (ss >> 2) ? 4096 : 0;
                const uint32_t m0 = (uint32_t)(ss & 3) * 32;
                const uint32_t m1 = m0 + 16;
                // tile0 (rows r0, r0+8)
                uint32_t A0 = cvt_pair(lds32((a0 + Aoff) ^ m0));
                uint32_t A1 = cvt_pair(lds32((a1 + Aoff) ^ m0));
                uint32_t A2 = cvt_pair(lds32((a0 + Aoff) ^ m1));
                uint32_t A3 = cvt_pair(lds32((a1 + Aoff) ^ m1));
                // tile1 (rows r0+16, r0+24)
                uint32_t B0 = cvt_pair(lds32((a2 + Aoff) ^ m0));
                uint32_t B1 = cvt_pair(lds32((a3 + Aoff) ^ m0));
                uint32_t B2 = cvt_pair(lds32((a2 + Aoff) ^ m1));
                uint32_t B3 = cvt_pair(lds32((a3 + Aoff) ^ m1));
                #pragma unroll
                for (int q = 0; q < 4; q++) {
                    const uint32_t xb = xq0 + (uint32_t)q * 1024 + Xoff;
                    uint32_t b0 = lds32(xb ^ m0);
                    uint32_t b1 = lds32(xb ^ m1);
                    mma16816(dd0[q], A0, A1, A2, A3, b0, b1);
                    mma16816(dd1[q], B0, B1, B2, B3, b0, b1);
                }
            }

            #pragma unroll
            for (int q = 0; q < 4; q++) {
                acc0[q][0] += dd0[q][0] * s0;
                acc0[q][1] += dd0[q][1] * s0;
                acc0[q][2] += dd0[q][2] * s1;
                acc0[q][3] += dd0[q][3] * s1;
                acc1[q][0] += dd1[q][0] * s2;
                acc1[q][1] += dd1[q][1] * s2;
                acc1[q][2] += dd1[q][2] * s3;
                acc1[q][3] += dd1[q][3] * s3;
            }

            mbar_arrive(mb + 32 + s * 8);   // buffer s free
        }

        // write fp32 partials for this (nt, ku) unit
        float* part = g_part[ku];
        const int n0 = nb + r0;
        #pragma unroll
        for (int q = 0; q < 4; q++) {
            int m0r = 8 * q + 2 * t;
            part[(size_t)m0r       * N_DIM + n0     ] = acc0[q][0];
            part[(size_t)(m0r + 1) * N_DIM + n0     ] = acc0[q][1];
            part[(size_t)m0r       * N_DIM + n0 + 8 ] = acc0[q][2];
            part[(size_t)(m0r + 1) * N_DIM + n0 + 8 ] = acc0[q][3];
            part[(size_t)m0r       * N_DIM + n0 + 16] = acc1[q][0];
            part[(size_t)(m0r + 1) * N_DIM + n0 + 16] = acc1[q][1];
            part[(size_t)m0r       * N_DIM + n0 + 24] = acc1[q][2];
            part[(size_t)(m0r + 1) * N_DIM + n0 + 24] = acc1[q][3];
        }
    }
}

typedef CUresult (*EncFn)(CUtensorMap*, CUtensorMapDataType, cuuint32_t, void*,
                          const cuuint64_t*, const cuuint64_t*, const cuuint32_t*,
                          const cuuint32_t*, CUtensorMapInterleave, CUtensorMapSwizzle,
                          CUtensorMapL2promotion, CUtensorMapFloatOOBfill);

extern "C" void kernel_launch(void* const* d_in, const int* in_sizes, int n_in,
                              void* d_out, int out_size) {
    const float* x  = (const float*)d_in[0];
    void*        wp = (void*)d_in[1];
    const float* sc = (const float*)d_in[2];
    float*       out = (float*)d_out;

    EncFn enc = nullptr;
    cudaDriverEntryPointQueryResult qr;
    cudaGetDriverEntryPoint("cuTensorMapEncodeTiled", (void**)&enc,
                            cudaEnableDefault, &qr);

    void* xsym = nullptr;
    cudaGetSymbolAddress(&xsym, g_x16);

    CUtensorMap tmA, tmX;
    {
        cuuint64_t dims[2]   = {KW, N_DIM};
        cuuint64_t stride[1] = {KW * 4};
        cuuint32_t box[2]    = {32, 128};          // 128 B x 128 rows
        cuuint32_t es[2]     = {1, 1};
        enc(&tmA, CU_TENSOR_MAP_DATA_TYPE_INT32, 2, wp, dims, stride, box, es,
            CU_TENSOR_MAP_INTERLEAVE_NONE, CU_TENSOR_MAP_SWIZZLE_128B,
            CU_TENSOR_MAP_L2_PROMOTION_L2_128B, CU_TENSOR_MAP_FLOAT_OOB_FILL_NONE);
    }
    {
        cuuint64_t dims[2]   = {K_DIM, M_DIM};
        cuuint64_t stride[1] = {K_DIM * 2};
        cuuint32_t box[2]    = {64, 32};           // 128 B x 32 rows
        cuuint32_t es[2]     = {1, 1};
        enc(&tmX, CU_TENSOR_MAP_DATA_TYPE_UINT16, 2, xsym, dims, stride, box, es,
            CU_TENSOR_MAP_INTERLEAVE_NONE, CU_TENSOR_MAP_SWIZZLE_128B,
            CU_TENSOR_MAP_L2_PROMOTION_L2_128B, CU_TENSOR_MAP_FLOAT_OOB_FILL_NONE);
    }

    cvt_x_kernel<<<128, 256>>>(x);

    cudaFuncSetAttribute(w4a16_mma_kernel,
                         cudaFuncAttributeMaxDynamicSharedMemorySize, SMEM_TOTAL);
    w4a16_mma_kernel<<<GRID, 160, SMEM_TOTAL>>>(tmA, tmX, sc);

    finalize_kernel<<<(M_DIM * N_DIM / 4 + 255) / 256, 256>>>(out);
}